// round 11
// baseline (speedup 1.0000x reference)
#include <cuda_runtime.h>
#include <cuda_bf16.h>
#include <cuda_fp16.h>
#include <math.h>
#include <stdint.h>

#define MAXN 100000
#define MAXE 1600000
#define EPS 1e-5f
#define CAP 96

__device__ float g_bufA[MAXN * 128];
__device__ float g_bufB[MAXN * 256];
__device__ int   g_cnt[MAXN];
__device__ int   g_colpad[MAXN * CAP];
__device__ float g_sum[448];
__device__ float g_sumsq[448];
__device__ uint8_t g_wimg[147456];

__device__ __forceinline__ uint32_t smem_to_u32(const void* smem_ptr) {
    uint32_t addr;
    asm("{ .reg .u64 tmp; cvta.to.shared.u64 tmp, %1; cvt.u32.u64 %0, tmp; }"
        : "=r"(addr) : "l"(smem_ptr));
    return addr;
}

__device__ __forceinline__ void ldmx4(uint32_t* r, uint32_t addr) {
    asm volatile(
        "ldmatrix.sync.aligned.m8n8.x4.shared.b16 {%0,%1,%2,%3}, [%4];"
        : "=r"(r[0]), "=r"(r[1]), "=r"(r[2]), "=r"(r[3]) : "r"(addr));
}

__device__ __forceinline__ void ldmx4t(uint32_t* r, uint32_t addr) {
    asm volatile(
        "ldmatrix.sync.aligned.m8n8.x4.trans.shared.b16 {%0,%1,%2,%3}, [%4];"
        : "=r"(r[0]), "=r"(r[1]), "=r"(r[2]), "=r"(r[3]) : "r"(addr));
}

__device__ __forceinline__ void mma_f16(float* c, const uint32_t* a,
                                        const uint32_t* b) {
    asm volatile(
        "mma.sync.aligned.m16n8k16.row.col.f32.f16.f16.f32 "
        "{%0,%1,%2,%3}, {%4,%5,%6,%7}, {%8,%9}, {%0,%1,%2,%3};"
        : "+f"(c[0]), "+f"(c[1]), "+f"(c[2]), "+f"(c[3])
        : "r"(a[0]), "r"(a[1]), "r"(a[2]), "r"(a[3]), "r"(b[0]), "r"(b[1]));
}

__device__ __forceinline__ void cp16(uint32_t dst, const void* src) {
    asm volatile("cp.async.cg.shared.global [%0], [%1], 16;"
                 :: "r"(dst), "l"(src) : "memory");
}
#define CP_COMMIT() asm volatile("cp.async.commit_group;" ::: "memory")
#define CP_WAIT0()  asm volatile("cp.async.wait_group 0;" ::: "memory")

__device__ __forceinline__ void wprep_one(const float* __restrict__ W,
                                          uint8_t* __restrict__ img,
                                          int idx, int K, int N, int NBLK) {
    int k = idx / N, n = idx % N;
    __half h = __float2half_rn(W[idx]);
    int nblk = n / NBLK, nloc = n % NBLK;
    uint32_t addr = (uint32_t)nblk * (uint32_t)(K * NBLK * 2) +
                    (uint32_t)k * (uint32_t)(NBLK * 2) +
                    (uint32_t)(((nloc >> 3) ^ (k & 7)) << 4) +
                    (uint32_t)((nloc * 2) & 15);
    *(__half*)(img + addr) = h;
}

// prep: zero counters/stats + all W fp16 swizzled images
__global__ void prep_kernel(const float* __restrict__ W1,
                            const float* __restrict__ W2,
                            const float* __restrict__ W3,
                            uint8_t* __restrict__ wimg, int n, int nb) {
    int b = blockIdx.x, t = threadIdx.x;
    if (b < nb) {
        int i = b * 256 + t;
        if (i < n) g_cnt[i] = 0;
        if (b == 0) { g_sum[t] = 0.f; g_sumsq[t] = 0.f; }
        if (b == 1 && t < 192) { g_sum[256 + t] = 0.f; g_sumsq[256 + t] = 0.f; }
    } else if (b < nb + 128) {
        int idx = (b - nb) * 256 + t;
        wprep_one(W1, wimg + 0, idx, 128, 256, 128);
    } else if (b < nb + 256) {
        int idx = (b - nb - 128) * 256 + t;
        wprep_one(W2, wimg + 65536, idx, 256, 128, 128);
    } else {
        int idx = (b - nb - 256) * 256 + t;
        if (idx < 8192)
            wprep_one(W3, wimg + 131072, idx, 128, 64, 64);
    }
}

// combo: scatter (4 edges/thread) || x->fp16
__global__ __launch_bounds__(256)
void combo_kernel(const int* __restrict__ src, const int* __restrict__ dst,
                  int E, int eb4,
                  const float* __restrict__ x, __half* __restrict__ x16,
                  int ntot16) {
    int b = blockIdx.x, t = threadIdx.x;
    if (b < eb4) {
        int base = (b * 256 + t) * 4;
        if (base < E) {
            int4 s4 = *(const int4*)(src + base);
            int4 d4 = *(const int4*)(dst + base);
            int ds[4] = {d4.x, d4.y, d4.z, d4.w};
            int ss[4] = {s4.x, s4.y, s4.z, s4.w};
#pragma unroll
            for (int j = 0; j < 4; j++) {
                int p = atomicAdd(&g_cnt[ds[j]], 1);
                if (p < CAP) g_colpad[(size_t)ds[j] * CAP + p] = ss[j];
            }
        }
    } else {
        int xi = (b - eb4) * 256 + t;
        if (xi < ntot16) {
            int base = xi * 8;
            float4 f0 = *(const float4*)(x + base);
            float4 f1 = *(const float4*)(x + base + 4);
            uint4 o;
            *(__half2*)&o.x = __floats2half2_rn(f0.x, f0.y);
            *(__half2*)&o.y = __floats2half2_rn(f0.z, f0.w);
            *(__half2*)&o.z = __floats2half2_rn(f1.x, f1.y);
            *(__half2*)&o.w = __floats2half2_rn(f1.z, f1.w);
            *(uint4*)(x16 + base) = o;
        }
    }
}

__global__ __launch_bounds__(1024)
void agg128_stats_f16_kernel(const __half* __restrict__ xw,
                             float* __restrict__ out,
                             float* __restrict__ psum,
                             float* __restrict__ psumsq, int n) {
    __shared__ float sv[32][128];
    int wid = threadIdx.x >> 5, lane = threadIdx.x & 31;
    int node = blockIdx.x * 32 + wid;
    float4 acc = make_float4(0.f, 0.f, 0.f, 0.f);
    if (node < n) {
        int cd = g_cnt[node];
        float di = rsqrtf((float)(cd + 1));
        {
            uint2 p = *(const uint2*)(xw + (size_t)node * 128 + lane * 4);
            float2 a = __half22float2(*(const __half2*)&p.x);
            float2 b = __half22float2(*(const __half2*)&p.y);
            acc.x = di * a.x; acc.y = di * a.y;
            acc.z = di * b.x; acc.w = di * b.y;
        }
        int m = cd < CAP ? cd : CAP;
        const int* cols = g_colpad + (size_t)node * CAP;
        int e = 0;
        for (; e + 8 <= m; e += 8) {
            int s = 0; float w = 0.f;
            if (lane < 8) {
                s = cols[e + lane];
                w = rsqrtf((float)(g_cnt[s] + 1));
            }
#pragma unroll
            for (int j = 0; j < 8; j++) {
                int sj = __shfl_sync(0xffffffffu, s, j);
                float wj = __shfl_sync(0xffffffffu, w, j);
                uint2 p = *(const uint2*)(xw + (size_t)sj * 128 + lane * 4);
                float2 a = __half22float2(*(const __half2*)&p.x);
                float2 b = __half22float2(*(const __half2*)&p.y);
                acc.x += wj * a.x; acc.y += wj * a.y;
                acc.z += wj * b.x; acc.w += wj * b.y;
            }
        }
        for (; e < m; e++) {
            int sj = cols[e];
            float wj = rsqrtf((float)(g_cnt[sj] + 1));
            uint2 p = *(const uint2*)(xw + (size_t)sj * 128 + lane * 4);
            float2 a = __half22float2(*(const __half2*)&p.x);
            float2 b = __half22float2(*(const __half2*)&p.y);
            acc.x += wj * a.x; acc.y += wj * a.y;
            acc.z += wj * b.x; acc.w += wj * b.y;
        }
        acc.x *= di; acc.y *= di; acc.z *= di; acc.w *= di;
        *(float4*)(out + (size_t)node * 128 + lane * 4) = acc;
    }
    sv[wid][lane * 4 + 0] = acc.x;
    sv[wid][lane * 4 + 1] = acc.y;
    sv[wid][lane * 4 + 2] = acc.z;
    sv[wid][lane * 4 + 3] = acc.w;
    __syncthreads();
    int t = threadIdx.x;
    if (t < 128) {
        float s = 0.f, q = 0.f;
#pragma unroll
        for (int w2 = 0; w2 < 32; w2++) {
            float v = sv[w2][t];
            s += v; q += v * v;
        }
        atomicAdd(&psum[t], s);
        atomicAdd(&psumsq[t], q);
    }
}

__global__ __launch_bounds__(1024)
void agg64_stats_f16_kernel(const __half* __restrict__ xw,
                            float* __restrict__ out,
                            float* __restrict__ psum,
                            float* __restrict__ psumsq, int n) {
    __shared__ float sv[32][64];
    int wid = threadIdx.x >> 5, lane = threadIdx.x & 31;
    int node = blockIdx.x * 32 + wid;
    float2 acc = make_float2(0.f, 0.f);
    if (node < n) {
        int cd = g_cnt[node];
        float di = rsqrtf((float)(cd + 1));
        {
            uint32_t p = *(const uint32_t*)(xw + (size_t)node * 64 + lane * 2);
            float2 a = __half22float2(*(const __half2*)&p);
            acc.x = di * a.x; acc.y = di * a.y;
        }
        int m = cd < CAP ? cd : CAP;
        const int* cols = g_colpad + (size_t)node * CAP;
        int e = 0;
        for (; e + 8 <= m; e += 8) {
            int s = 0; float w = 0.f;
            if (lane < 8) {
                s = cols[e + lane];
                w = rsqrtf((float)(g_cnt[s] + 1));
            }
#pragma unroll
            for (int j = 0; j < 8; j++) {
                int sj = __shfl_sync(0xffffffffu, s, j);
                float wj = __shfl_sync(0xffffffffu, w, j);
                uint32_t p = *(const uint32_t*)(xw + (size_t)sj * 64 + lane * 2);
                float2 a = __half22float2(*(const __half2*)&p);
                acc.x += wj * a.x; acc.y += wj * a.y;
            }
        }
        for (; e < m; e++) {
            int sj = cols[e];
            float wj = rsqrtf((float)(g_cnt[sj] + 1));
            uint32_t p = *(const uint32_t*)(xw + (size_t)sj * 64 + lane * 2);
            float2 a = __half22float2(*(const __half2*)&p);
            acc.x += wj * a.x; acc.y += wj * a.y;
        }
        acc.x *= di; acc.y *= di;
        *(float2*)(out + (size_t)node * 64 + lane * 2) = acc;
    }
    sv[wid][lane * 2 + 0] = acc.x;
    sv[wid][lane * 2 + 1] = acc.y;
    __syncthreads();
    int t = threadIdx.x;
    if (t < 64) {
        float s = 0.f, q = 0.f;
#pragma unroll
        for (int w2 = 0; w2 < 32; w2++) {
            float v = sv[w2][t];
            s += v; q += v * v;
        }
        atomicAdd(&psum[t], s);
        atomicAdd(&psumsq[t], q);
    }
}

// fp16 tensor-core GEMM, 256 threads / 8 warps (2m x 4n), warp tile 64 x (NBLK/4).
// 2-stage cp.async pipeline (double-buffered W; total stages NITER*KCH <= 2).
// AGGIN 1: A tile computed on the fly as GCN aggregation of Av (x16 plane)
//          for this CTA's 128 rows (warp-per-row, gather via g_colpad). KCH==1.
// MODE 1: BN finalize of previous layer inlined; A'=sigmoid(A*scale+shift).
// STATS 1: per-column sum/sumsq of C. OUTF16: C stored fp16.
template <int NBLK, int NITER, int KCH, int INF16, int MODE, int STATS,
          int OUTF16, int AGGIN>
__global__ __launch_bounds__(256, 2)
void mma_gemm_kernel(const void* __restrict__ Av,
                     const uint8_t* __restrict__ wimg,
                     void* __restrict__ Cv,
                     const float* __restrict__ gamma,
                     const float* __restrict__ beta,
                     const float* __restrict__ psum_in,
                     const float* __restrict__ psumsq_in,
                     float* __restrict__ psum_out,
                     float* __restrict__ psumsq_out, int M) {
    extern __shared__ char dsm[];
    char* sm = (char*)(((uintptr_t)dsm + 1023) & ~(uintptr_t)1023);
    uint32_t sbase = smem_to_u32(sm);

    constexpr int WN = NBLK / 4;
    constexpr int NT = WN / 8;
    constexpr int NG = NT / 2;
    constexpr int K = KCH * 128;
    constexpr int N = NITER * NBLK;
    constexpr int TOTAL = NITER * KCH;   // <= 2
    constexpr int wchunk = 128 * NBLK * 2;
    const int OFF_A = 0;
    const int OFF_W = 32768;

    __shared__ float s_scale[256], s_shift[256];

    const float* Af = (const float*)Av;
    const __half* Ah = (const __half*)Av;

    int tid = threadIdx.x;
    int wid = tid >> 5, lane = tid & 31;
    int wm = (wid >> 2) * 64;
    int wn = (wid & 3) * WN;
    int mrow0 = blockIdx.y * 128;

    if (MODE == 1) {
        if (tid < K) {
            float invn = 1.f / (float)M;
            float mv = psum_in[tid] * invn;
            float var = psumsq_in[tid] * invn - mv * mv;
            float sc = gamma[tid] * rsqrtf(var + EPS);
            s_scale[tid] = sc;
            s_shift[tid] = beta[tid] - mv * sc;
        }
        __syncthreads();
    }

    int lrow = (lane & 7) + ((lane & 8) ? 8 : 0);
    int lsel = (lane >> 4) & 1;
    int arow[4];
#pragma unroll
    for (int mi = 0; mi < 4; mi++) arow[mi] = wm + mi * 16 + lrow;
    int kx = lane & 7;
    int g4 = lane >> 2, tig = lane & 3;

    // ---- standard A staging (fp16/fp32 plane, optional BN+sigmoid) ----
    auto stage_A = [&](int c) {
#pragma unroll
        for (int it = 0; it < 8; it++) {
            int u = tid + it * 256;
            int m = u >> 4, kc8 = u & 15;
            int row = mrow0 + m;
            uint32_t dst = sbase + OFF_A +
                           (uint32_t)(m * 256 + ((kc8 ^ (m & 7)) << 4));
            if (INF16 && MODE == 0) {
                if (row < M) cp16(dst, Ah + (size_t)row * K + c * 128 + kc8 * 8);
                else *(uint4*)(sm + (dst - sbase)) = make_uint4(0, 0, 0, 0);
            } else {
                uint4 o;
                if (row < M) {
                    float v[8];
                    if (INF16) {
                        uint4 p4 = *(const uint4*)(Ah + (size_t)row * K + c * 128 + kc8 * 8);
                        float2 t0 = __half22float2(*(const __half2*)&p4.x);
                        float2 t1 = __half22float2(*(const __half2*)&p4.y);
                        float2 t2 = __half22float2(*(const __half2*)&p4.z);
                        float2 t3 = __half22float2(*(const __half2*)&p4.w);
                        v[0] = t0.x; v[1] = t0.y; v[2] = t1.x; v[3] = t1.y;
                        v[4] = t2.x; v[5] = t2.y; v[6] = t3.x; v[7] = t3.y;
                    } else {
                        float4 f0 = *(const float4*)(Af + (size_t)row * K + c * 128 + kc8 * 8);
                        float4 f1 = *(const float4*)(Af + (size_t)row * K + c * 128 + kc8 * 8 + 4);
                        v[0] = f0.x; v[1] = f0.y; v[2] = f0.z; v[3] = f0.w;
                        v[4] = f1.x; v[5] = f1.y; v[6] = f1.z; v[7] = f1.w;
                    }
                    if (MODE == 1) {
#pragma unroll
                        for (int j = 0; j < 8; j++) {
                            int kg = c * 128 + kc8 * 8 + j;
                            float y = v[j] * s_scale[kg] + s_shift[kg];
                            v[j] = 1.f / (1.f + __expf(-y));
                        }
                    }
                    *(__half2*)&o.x = __floats2half2_rn(v[0], v[1]);
                    *(__half2*)&o.y = __floats2half2_rn(v[2], v[3]);
                    *(__half2*)&o.z = __floats2half2_rn(v[4], v[5]);
                    *(__half2*)&o.w = __floats2half2_rn(v[6], v[7]);
                } else {
                    o = make_uint4(0, 0, 0, 0);
                }
                *(uint4*)(sm + (dst - sbase)) = o;
            }
        }
    };

    // ---- fused agg staging: warp-per-row GCN aggregation into smem A ----
    auto stage_agg = [&]() {
#pragma unroll 1
        for (int rr = 0; rr < 16; rr++) {
            int m = wid * 16 + rr;
            int node = mrow0 + m;
            float4 acc = make_float4(0.f, 0.f, 0.f, 0.f);
            if (node < M) {
                int cd = g_cnt[node];
                float di = rsqrtf((float)(cd + 1));
                {
                    uint2 p = *(const uint2*)(Ah + (size_t)node * 128 + lane * 4);
                    float2 a = __half22float2(*(const __half2*)&p.x);
                    float2 b = __half22float2(*(const __half2*)&p.y);
                    acc.x = di * a.x; acc.y = di * a.y;
                    acc.z = di * b.x; acc.w = di * b.y;
                }
                int mm = cd < CAP ? cd : CAP;
                const int* cols = g_colpad + (size_t)node * CAP;
                int e = 0;
                for (; e + 8 <= mm; e += 8) {
                    int s = 0; float w = 0.f;
                    if (lane < 8) {
                        s = cols[e + lane];
                        w = rsqrtf((float)(g_cnt[s] + 1));
                    }
#pragma unroll
                    for (int j = 0; j < 8; j++) {
                        int sj = __shfl_sync(0xffffffffu, s, j);
                        float wj = __shfl_sync(0xffffffffu, w, j);
                        uint2 p = *(const uint2*)(Ah + (size_t)sj * 128 + lane * 4);
                        float2 a = __half22float2(*(const __half2*)&p.x);
                        float2 b = __half22float2(*(const __half2*)&p.y);
                        acc.x += wj * a.x; acc.y += wj * a.y;
                        acc.z += wj * b.x; acc.w += wj * b.y;
                    }
                }
                for (; e < mm; e++) {
                    int sj = cols[e];
                    float wj = rsqrtf((float)(g_cnt[sj] + 1));
                    uint2 p = *(const uint2*)(Ah + (size_t)sj * 128 + lane * 4);
                    float2 a = __half22float2(*(const __half2*)&p.x);
                    float2 b = __half22float2(*(const __half2*)&p.y);
                    acc.x += wj * a.x; acc.y += wj * a.y;
                    acc.z += wj * b.x; acc.w += wj * b.y;
                }
                acc.x *= di; acc.y *= di; acc.z *= di; acc.w *= di;
            }
            // lane holds features [lane*4, lane*4+4) of row m -> half of kc8 chunk
            int kc8 = lane >> 1;
            uint32_t off = (uint32_t)(m * 256 + ((kc8 ^ (m & 7)) << 4) +
                                      (lane & 1) * 8);
            uint2 o;
            *(__half2*)&o.x = __floats2half2_rn(acc.x, acc.y);
            *(__half2*)&o.y = __floats2half2_rn(acc.z, acc.w);
            *(uint2*)(sm + OFF_A + off) = o;
        }
    };

    auto issue_W = [&](int t, int buf) {
        int nb_ = t / KCH, c_ = t % KCH;
        const uint8_t* src = wimg +
            ((size_t)(blockIdx.x * NITER + nb_) * KCH + c_) * (size_t)wchunk;
#pragma unroll
        for (int i = 0; i < wchunk / (256 * 16); i++) {
            int off = (tid + i * 256) * 16;
            cp16(sbase + OFF_W + buf * wchunk + off, src + off);
        }
    };

    // ---- initial stage 0 (W prefetch overlaps A staging / aggregation) ----
    issue_W(0, 0);
    CP_COMMIT();
    if (AGGIN) stage_agg(); else stage_A(0);
    CP_WAIT0();
    __syncthreads();
    if (TOTAL > 1) {
        issue_W(1, 1);
        CP_COMMIT();
    }

    for (int nb = 0; nb < NITER; nb++) {
        float acc[4][NT][4];
#pragma unroll
        for (int mi = 0; mi < 4; mi++)
#pragma unroll
            for (int nj = 0; nj < NT; nj++)
#pragma unroll
                for (int q = 0; q < 4; q++) acc[mi][nj][q] = 0.f;

        for (int c = 0; c < KCH; c++) {
            int t = nb * KCH + c;
            if (t > 0) {
                __syncthreads();
                if (KCH == 2 && c == 1) stage_A(1);
                CP_WAIT0();
                __syncthreads();
            }
            int buf = t & 1;
#pragma unroll
            for (int s = 0; s < 8; s++) {
                uint32_t a[4][4];
                int achunk = s * 2 + lsel;
#pragma unroll
                for (int mi = 0; mi < 4; mi++) {
                    uint32_t aoff = (uint32_t)(arow[mi] * 256 +
                                               ((achunk ^ (arow[mi] & 7)) << 4));
                    ldmx4(a[mi], sbase + OFF_A + aoff);
                }
                uint32_t wr[NT * 2];
                int kr = s * 16 + lrow;
#pragma unroll
                for (int grp = 0; grp < NG; grp++) {
                    int cn = (wn + grp * 16 + lsel * 8) >> 3;
                    uint32_t woff = (uint32_t)(kr * (NBLK * 2) + ((cn ^ kx) << 4));
                    ldmx4t(&wr[grp * 4], sbase + OFF_W + buf * wchunk + woff);
                }
#pragma unroll
                for (int mi = 0; mi < 4; mi++)
#pragma unroll
                    for (int nj = 0; nj < NT; nj++)
                        mma_f16(acc[mi][nj], a[mi], &wr[nj * 2]);
            }
        }

        int bcol = (blockIdx.x * NITER + nb) * NBLK;
#pragma unroll
        for (int mi = 0; mi < 4; mi++) {
            int row = mrow0 + wm + mi * 16 + g4;
#pragma unroll
            for (int nj = 0; nj < NT; nj++) {
                int col = bcol + wn + nj * 8 + tig * 2;
                if (OUTF16) {
                    __half* Ch = (__half*)Cv;
                    if (row < M)
                        *(__half2*)(Ch + (size_t)row * N + col) =
                            __floats2half2_rn(acc[mi][nj][0], acc[mi][nj][1]);
                    if (row + 8 < M)
                        *(__half2*)(Ch + (size_t)(row + 8) * N + col) =
                            __floats2half2_rn(acc[mi][nj][2], acc[mi][nj][3]);
                } else {
                    float* Cf = (float*)Cv;
                    if (row < M)
                        *(float2*)(Cf + (size_t)row * N + col) =
                            make_float2(acc[mi][nj][0], acc[mi][nj][1]);
                    if (row + 8 < M)
                        *(float2*)(Cf + (size_t)(row + 8) * N + col) =
                            make_float2(acc[mi][nj][2], acc[mi][nj][3]);
                }
            }
        }

        if (STATS) {
            __shared__ float sp_s[8][WN], sp_q[8][WN];
#pragma unroll
            for (int nj = 0; nj < NT; nj++) {
                float c0 = 0.f, c1 = 0.f, q0 = 0.f, q1 = 0.f;
#pragma unroll
                for (int mi = 0; mi < 4; mi++) {
                    c0 += acc[mi][nj][0] + acc[mi][nj][2];
                    c1 += acc[mi][nj][1] + acc[mi][nj][3];
                    q0 += acc[mi][nj][0] * acc[mi][nj][0] +
                          acc[mi][nj][2] * acc[mi][nj][2];
                    q1 += acc[mi][nj][1] * acc[mi][nj][1] +
                          acc[mi][nj][3] * acc[mi][nj][3];
                }
#pragma unroll
                for (int o = 4; o < 32; o <<= 1) {
                    c0 += __shfl_xor_sync(0xffffffffu, c0, o);
                    c1 += __shfl_xor_sync(0xffffffffu, c1, o);
                    q0 += __shfl_xor_sync(0xffffffffu, q0, o);
                    q1 += __shfl_xor_sync(0xffffffffu, q1, o);
                }
                if (lane < 4) {
                    sp_s[wid][nj * 8 + lane * 2 + 0] = c0;
                    sp_s[wid][nj * 8 + lane * 2 + 1] = c1;
                    sp_q[wid][nj * 8 + lane * 2 + 0] = q0;
                    sp_q[wid][nj * 8 + lane * 2 + 1] = q1;
                }
            }
            __syncthreads();
            if (tid < NBLK) {
                int p = tid / WN, lc = tid % WN;
                float s = sp_s[p][lc] + sp_s[p + 4][lc];
                float q = sp_q[p][lc] + sp_q[p + 4][lc];
                atomicAdd(&psum_out[bcol + tid], s);
                atomicAdd(&psumsq_out[bcol + tid], q);
            }
            __syncthreads();
        }
    }
}

// decode with BN3 finalize inlined
__global__ void decode_kernel(const float* __restrict__ z,
                              const int* __restrict__ pe,
                              const int* __restrict__ ne,
                              const float* __restrict__ gamma,
                              const float* __restrict__ beta,
                              const float* __restrict__ psum,
                              const float* __restrict__ psumsq,
                              float* __restrict__ out, int P, int Q, int n) {
    __shared__ float s_sc[64], s_sh[64];
    int tid = threadIdx.x;
    if (tid < 64) {
        float invn = 1.f / (float)n;
        float m = psum[tid] * invn;
        float var = psumsq[tid] * invn - m * m;
        float sc = gamma[tid] * rsqrtf(var + EPS);
        s_sc[tid] = sc;
        s_sh[tid] = beta[tid] - m * sc;
    }
    __syncthreads();
    int idx = blockIdx.x * blockDim.x + tid;
    int eg = idx >> 4;
    int l = idx & 15;
    if (eg >= P + Q) return;
    int a, b;
    if (eg < P) { a = pe[eg];     b = pe[P + eg]; }
    else        { int e = eg - P; a = ne[e]; b = ne[Q + e]; }
    float4 sc = ((const float4*)s_sc)[l];
    float4 sh = ((const float4*)s_sh)[l];
    float4 xa = ((const float4*)(z + (size_t)a * 64))[l];
    float4 xb = ((const float4*)(z + (size_t)b * 64))[l];
    xa.x = xa.x * sc.x + sh.x; xa.y = xa.y * sc.y + sh.y;
    xa.z = xa.z * sc.z + sh.z; xa.w = xa.w * sc.w + sh.w;
    xb.x = xb.x * sc.x + sh.x; xb.y = xb.y * sc.y + sh.y;
    xb.z = xb.z * sc.z + sh.z; xb.w = xb.w * sc.w + sh.w;
    float s = xa.x * xb.x + xa.y * xb.y + xa.z * xb.z + xa.w * xb.w;
    s += __shfl_xor_sync(0xffffffffu, s, 8);
    s += __shfl_xor_sync(0xffffffffu, s, 4);
    s += __shfl_xor_sync(0xffffffffu, s, 2);
    s += __shfl_xor_sync(0xffffffffu, s, 1);
    if (l == 0) out[eg] = s;
}

extern "C" void kernel_launch(void* const* d_in, const int* in_sizes, int n_in,
                              void* d_out, int out_size) {
    const float* x  = (const float*)d_in[0];
    const int*   ei = (const int*)d_in[1];
    const int*   pe = (const int*)d_in[2];
    const int*   ne = (const int*)d_in[3];
    const float* W1 = (const float*)d_in[4];
    const float* g1 = (const float*)d_in[6];
    const float* be1= (const float*)d_in[7];
    const float* W2 = (const float*)d_in[8];
    const float* g2 = (const float*)d_in[10];
    const float* be2= (const float*)d_in[11];
    const float* W3 = (const float*)d_in[12];
    const float* g3 = (const float*)d_in[14];
    const float* be3= (const float*)d_in[15];
    // biases b1/b2/b3 cancel exactly under BatchNorm (mean subtraction); skipped.

    int N = in_sizes[0] / 128;
    int E = in_sizes[1] / 2;
    int P = in_sizes[2] / 2;
    int Q = in_sizes[3] / 2;

    float* bufA; float* bufB; uint8_t* wimg; float* sum; float* sumsq;
    cudaGetSymbolAddress((void**)&bufA, g_bufA);
    cudaGetSymbolAddress((void**)&bufB, g_bufB);
    cudaGetSymbolAddress((void**)&wimg, g_wimg);
    cudaGetSymbolAddress((void**)&sum, g_sum);
    cudaGetSymbolAddress((void**)&sumsq, g_sumsq);

    __half* x16 = (__half*)bufA;                       // N x 128 fp16
    __half* h1  = (__half*)bufB;                       // N x 256 fp16 (gemm1 out)
    __half* h2  = (__half*)(bufB + 12800000);          // N x 128 fp16 (gemm2 out)
    float*  b2  = bufA;                                // N x 128 fp32 (agg2 out; x16 dead by then)
    __half* h3  = (__half*)(bufB + 19200000);          // N x 64 fp16 (gemm3 out)
    float*  z   = bufB;                                // N x 64 fp32 (agg3 out)

    float* out = (float*)d_out;

    int nb = (N + 255) / 256;
    int eb4 = (E / 4 + 255) / 256;
    int xb = (N * 16 + 255) / 256;
    int aggB1024 = (N + 31) / 32;
    int mtiles = (N + 127) / 128;

    const int SMEM_L1 = 1024 + 32768 + 2 * 32768;   // 99328 (A + 2x W128)
    const int SMEM_L2 = 1024 + 32768 + 2 * 32768;   // 99328
    const int SMEM_L3 = 1024 + 32768 + 16384;       // 50176 (1 stage)
    cudaFuncSetAttribute((const void*)mma_gemm_kernel<128, 2, 1, 1, 0, 1, 1, 1>,
                         cudaFuncAttributeMaxDynamicSharedMemorySize, SMEM_L1);
    cudaFuncSetAttribute((const void*)mma_gemm_kernel<128, 1, 2, 1, 1, 0, 1, 0>,
                         cudaFuncAttributeMaxDynamicSharedMemorySize, SMEM_L2);
    cudaFuncSetAttribute((const void*)mma_gemm_kernel<64, 1, 1, 0, 1, 0, 1, 0>,
                         cudaFuncAttributeMaxDynamicSharedMemorySize, SMEM_L3);

    // ---- prep (zero + W images) / combo (scatter || x->fp16) ----
    prep_kernel<<<nb + 288, 256>>>(W1, W2, W3, wimg, N, nb);               // 0
    combo_kernel<<<eb4 + xb, 256>>>(ei, ei + E, E, eb4, x, x16, N * 16);   // 1

    // ---- Layer 1: FUSED agg+GEMM fp16 (stats -> sum[0:256]) ----
    mma_gemm_kernel<128, 2, 1, 1, 0, 1, 1, 1><<<dim3(1, mtiles), 256, SMEM_L1>>>(
        x16, wimg + 0, h1, nullptr, nullptr, nullptr, nullptr,
        sum, sumsq, N);                                                    // 2

    // ---- Layer 2: GEMM (BN1+sigmoid inline) -> agg (stats -> sum[256:384]) ----
    mma_gemm_kernel<128, 1, 2, 1, 1, 0, 1, 0><<<dim3(1, mtiles), 256, SMEM_L2>>>(
        h1, wimg + 65536, h2, g1, be1, sum, sumsq,
        nullptr, nullptr, N);                                              // 3
    agg128_stats_f16_kernel<<<aggB1024, 1024>>>(h2, b2, sum + 256, sumsq + 256, N);  // 4

    // ---- Layer 3: GEMM (BN2+sigmoid inline) -> agg64 (stats -> sum[384:448]) ----
    mma_gemm_kernel<64, 1, 1, 0, 1, 0, 1, 0><<<dim3(1, mtiles), 256, SMEM_L3>>>(
        b2, wimg + 131072, h3, g2, be2, sum + 256, sumsq + 256,
        nullptr, nullptr, N);                                              // 5
    agg64_stats_f16_kernel<<<aggB1024, 1024>>>(h3, z, sum + 384, sumsq + 384, N);    // 6

    // ---- Decode (BN3 finalize + affine inlined, fp32 z) ----
    {
        int tot = (P + Q) * 16;
        decode_kernel<<<(tot + 255) / 256, 256>>>(
            z, pe, ne, g3, be3, sum + 384, sumsq + 384, out, P, Q, N);     // 7
    }
}

// round 16
// speedup vs baseline: 1.1984x; 1.1984x over previous
#include <cuda_runtime.h>
#include <cuda_bf16.h>
#include <cuda_fp16.h>
#include <math.h>
#include <stdint.h>

#define MAXN 100000
#define MAXE 1600000
#define EPS 1e-5f
#define CAP 96

__device__ float g_bufA[MAXN * 128];
__device__ float g_bufB[MAXN * 256];
__device__ int   g_cnt[MAXN];
__device__ int   g_colpad[MAXN * CAP];
__device__ float g_sum[448];
__device__ float g_sumsq[448];
__device__ uint8_t g_wimg[147456];

__device__ __forceinline__ uint32_t smem_to_u32(const void* smem_ptr) {
    uint32_t addr;
    asm("{ .reg .u64 tmp; cvta.to.shared.u64 tmp, %1; cvt.u32.u64 %0, tmp; }"
        : "=r"(addr) : "l"(smem_ptr));
    return addr;
}

__device__ __forceinline__ void ldmx4(uint32_t* r, uint32_t addr) {
    asm volatile(
        "ldmatrix.sync.aligned.m8n8.x4.shared.b16 {%0,%1,%2,%3}, [%4];"
        : "=r"(r[0]), "=r"(r[1]), "=r"(r[2]), "=r"(r[3]) : "r"(addr));
}

__device__ __forceinline__ void ldmx4t(uint32_t* r, uint32_t addr) {
    asm volatile(
        "ldmatrix.sync.aligned.m8n8.x4.trans.shared.b16 {%0,%1,%2,%3}, [%4];"
        : "=r"(r[0]), "=r"(r[1]), "=r"(r[2]), "=r"(r[3]) : "r"(addr));
}

__device__ __forceinline__ void mma_f16(float* c, const uint32_t* a,
                                        const uint32_t* b) {
    asm volatile(
        "mma.sync.aligned.m16n8k16.row.col.f32.f16.f16.f32 "
        "{%0,%1,%2,%3}, {%4,%5,%6,%7}, {%8,%9}, {%0,%1,%2,%3};"
        : "+f"(c[0]), "+f"(c[1]), "+f"(c[2]), "+f"(c[3])
        : "r"(a[0]), "r"(a[1]), "r"(a[2]), "r"(a[3]), "r"(b[0]), "r"(b[1]));
}

__device__ __forceinline__ void cp16(uint32_t dst, const void* src) {
    asm volatile("cp.async.cg.shared.global [%0], [%1], 16;"
                 :: "r"(dst), "l"(src) : "memory");
}
#define CP_COMMIT() asm volatile("cp.async.commit_group;" ::: "memory")
#define CP_WAIT0()  asm volatile("cp.async.wait_group 0;" ::: "memory")

__device__ __forceinline__ void wprep_one(const float* __restrict__ W,
                                          uint8_t* __restrict__ img,
                                          int idx, int K, int N, int NBLK) {
    int k = idx / N, n = idx % N;
    __half h = __float2half_rn(W[idx]);
    int nblk = n / NBLK, nloc = n % NBLK;
    uint32_t addr = (uint32_t)nblk * (uint32_t)(K * NBLK * 2) +
                    (uint32_t)k * (uint32_t)(NBLK * 2) +
                    (uint32_t)(((nloc >> 3) ^ (k & 7)) << 4) +
                    (uint32_t)((nloc * 2) & 15);
    *(__half*)(img + addr) = h;
}

__global__ void prep_kernel(const float* __restrict__ W1,
                            const float* __restrict__ W2,
                            const float* __restrict__ W3,
                            uint8_t* __restrict__ wimg, int n, int nb) {
    int b = blockIdx.x, t = threadIdx.x;
    if (b < nb) {
        int i = b * 256 + t;
        if (i < n) g_cnt[i] = 0;
        if (b == 0) { g_sum[t] = 0.f; g_sumsq[t] = 0.f; }
        if (b == 1 && t < 192) { g_sum[256 + t] = 0.f; g_sumsq[256 + t] = 0.f; }
    } else if (b < nb + 128) {
        int idx = (b - nb) * 256 + t;
        wprep_one(W1, wimg + 0, idx, 128, 256, 128);
    } else if (b < nb + 256) {
        int idx = (b - nb - 128) * 256 + t;
        wprep_one(W2, wimg + 65536, idx, 256, 128, 128);
    } else {
        int idx = (b - nb - 256) * 256 + t;
        if (idx < 8192)
            wprep_one(W3, wimg + 131072, idx, 128, 64, 64);
    }
}

__global__ __launch_bounds__(256)
void combo_kernel(const int* __restrict__ src, const int* __restrict__ dst,
                  int E, int eb4,
                  const float* __restrict__ x, __half* __restrict__ x16,
                  int ntot16) {
    int b = blockIdx.x, t = threadIdx.x;
    if (b < eb4) {
        int base = (b * 256 + t) * 4;
        if (base < E) {
            int4 s4 = *(const int4*)(src + base);
            int4 d4 = *(const int4*)(dst + base);
            int ds[4] = {d4.x, d4.y, d4.z, d4.w};
            int ss[4] = {s4.x, s4.y, s4.z, s4.w};
#pragma unroll
            for (int j = 0; j < 4; j++) {
                int p = atomicAdd(&g_cnt[ds[j]], 1);
                if (p < CAP) g_colpad[(size_t)ds[j] * CAP + p] = ss[j];
            }
        }
    } else {
        int xi = (b - eb4) * 256 + t;
        if (xi < ntot16) {
            int base = xi * 8;
            float4 f0 = *(const float4*)(x + base);
            float4 f1 = *(const float4*)(x + base + 4);
            uint4 o;
            *(__half2*)&o.x = __floats2half2_rn(f0.x, f0.y);
            *(__half2*)&o.y = __floats2half2_rn(f0.z, f0.w);
            *(__half2*)&o.z = __floats2half2_rn(f1.x, f1.y);
            *(__half2*)&o.w = __floats2half2_rn(f1.z, f1.w);
            *(uint4*)(x16 + base) = o;
        }
    }
}

__global__ __launch_bounds__(256)
void agg128_f16_kernel(const __half* __restrict__ xw,
                       __half* __restrict__ out, int n) {
    int node = (blockIdx.x * blockDim.x + threadIdx.x) >> 5;
    int lane = threadIdx.x & 31;
    if (node >= n) return;
    int cd = g_cnt[node];
    float di = rsqrtf((float)(cd + 1));
    float4 acc;
    {
        uint2 p = *(const uint2*)(xw + (size_t)node * 128 + lane * 4);
        float2 a = __half22float2(*(const __half2*)&p.x);
        float2 b = __half22float2(*(const __half2*)&p.y);
        acc.x = di * a.x; acc.y = di * a.y; acc.z = di * b.x; acc.w = di * b.y;
    }
    int m = cd < CAP ? cd : CAP;
    const int* cols = g_colpad + (size_t)node * CAP;
    int e = 0;
    for (; e + 8 <= m; e += 8) {
        int s = 0; float w = 0.f;
        if (lane < 8) {
            s = cols[e + lane];
            w = rsqrtf((float)(g_cnt[s] + 1));
        }
#pragma unroll
        for (int j = 0; j < 8; j++) {
            int sj = __shfl_sync(0xffffffffu, s, j);
            float wj = __shfl_sync(0xffffffffu, w, j);
            uint2 p = *(const uint2*)(xw + (size_t)sj * 128 + lane * 4);
            float2 a = __half22float2(*(const __half2*)&p.x);
            float2 b = __half22float2(*(const __half2*)&p.y);
            acc.x += wj * a.x; acc.y += wj * a.y;
            acc.z += wj * b.x; acc.w += wj * b.y;
        }
    }
    for (; e < m; e++) {
        int sj = cols[e];
        float wj = rsqrtf((float)(g_cnt[sj] + 1));
        uint2 p = *(const uint2*)(xw + (size_t)sj * 128 + lane * 4);
        float2 a = __half22float2(*(const __half2*)&p.x);
        float2 b = __half22float2(*(const __half2*)&p.y);
        acc.x += wj * a.x; acc.y += wj * a.y;
        acc.z += wj * b.x; acc.w += wj * b.y;
    }
    uint2 o;
    *(__half2*)&o.x = __floats2half2_rn(acc.x * di, acc.y * di);
    *(__half2*)&o.y = __floats2half2_rn(acc.z * di, acc.w * di);
    *(uint2*)(out + (size_t)node * 128 + lane * 4) = o;
}

__global__ __launch_bounds__(1024)
void agg128_stats_f16_kernel(const __half* __restrict__ xw,
                             float* __restrict__ out,
                             float* __restrict__ psum,
                             float* __restrict__ psumsq, int n) {
    __shared__ float sv[32][128];
    int wid = threadIdx.x >> 5, lane = threadIdx.x & 31;
    int node = blockIdx.x * 32 + wid;
    float4 acc = make_float4(0.f, 0.f, 0.f, 0.f);
    if (node < n) {
        int cd = g_cnt[node];
        float di = rsqrtf((float)(cd + 1));
        {
            uint2 p = *(const uint2*)(xw + (size_t)node * 128 + lane * 4);
            float2 a = __half22float2(*(const __half2*)&p.x);
            float2 b = __half22float2(*(const __half2*)&p.y);
            acc.x = di * a.x; acc.y = di * a.y;
            acc.z = di * b.x; acc.w = di * b.y;
        }
        int m = cd < CAP ? cd : CAP;
        const int* cols = g_colpad + (size_t)node * CAP;
        int e = 0;
        for (; e + 8 <= m; e += 8) {
            int s = 0; float w = 0.f;
            if (lane < 8) {
                s = cols[e + lane];
                w = rsqrtf((float)(g_cnt[s] + 1));
            }
#pragma unroll
            for (int j = 0; j < 8; j++) {
                int sj = __shfl_sync(0xffffffffu, s, j);
                float wj = __shfl_sync(0xffffffffu, w, j);
                uint2 p = *(const uint2*)(xw + (size_t)sj * 128 + lane * 4);
                float2 a = __half22float2(*(const __half2*)&p.x);
                float2 b = __half22float2(*(const __half2*)&p.y);
                acc.x += wj * a.x; acc.y += wj * a.y;
                acc.z += wj * b.x; acc.w += wj * b.y;
            }
        }
        for (; e < m; e++) {
            int sj = cols[e];
            float wj = rsqrtf((float)(g_cnt[sj] + 1));
            uint2 p = *(const uint2*)(xw + (size_t)sj * 128 + lane * 4);
            float2 a = __half22float2(*(const __half2*)&p.x);
            float2 b = __half22float2(*(const __half2*)&p.y);
            acc.x += wj * a.x; acc.y += wj * a.y;
            acc.z += wj * b.x; acc.w += wj * b.y;
        }
        acc.x *= di; acc.y *= di; acc.z *= di; acc.w *= di;
        *(float4*)(out + (size_t)node * 128 + lane * 4) = acc;
    }
    sv[wid][lane * 4 + 0] = acc.x;
    sv[wid][lane * 4 + 1] = acc.y;
    sv[wid][lane * 4 + 2] = acc.z;
    sv[wid][lane * 4 + 3] = acc.w;
    __syncthreads();
    int t = threadIdx.x;
    if (t < 128) {
        float s = 0.f, q = 0.f;
#pragma unroll
        for (int w2 = 0; w2 < 32; w2++) {
            float v = sv[w2][t];
            s += v; q += v * v;
        }
        atomicAdd(&psum[t], s);
        atomicAdd(&psumsq[t], q);
    }
}

__global__ __launch_bounds__(1024)
void agg64_stats_f16_kernel(const __half* __restrict__ xw,
                            float* __restrict__ out,
                            float* __restrict__ psum,
                            float* __restrict__ psumsq, int n) {
    __shared__ float sv[32][64];
    int wid = threadIdx.x >> 5, lane = threadIdx.x & 31;
    int node = blockIdx.x * 32 + wid;
    float2 acc = make_float2(0.f, 0.f);
    if (node < n) {
        int cd = g_cnt[node];
        float di = rsqrtf((float)(cd + 1));
        {
            uint32_t p = *(const uint32_t*)(xw + (size_t)node * 64 + lane * 2);
            float2 a = __half22float2(*(const __half2*)&p);
            acc.x = di * a.x; acc.y = di * a.y;
        }
        int m = cd < CAP ? cd : CAP;
        const int* cols = g_colpad + (size_t)node * CAP;
        int e = 0;
        for (; e + 8 <= m; e += 8) {
            int s = 0; float w = 0.f;
            if (lane < 8) {
                s = cols[e + lane];
                w = rsqrtf((float)(g_cnt[s] + 1));
            }
#pragma unroll
            for (int j = 0; j < 8; j++) {
                int sj = __shfl_sync(0xffffffffu, s, j);
                float wj = __shfl_sync(0xffffffffu, w, j);
                uint32_t p = *(const uint32_t*)(xw + (size_t)sj * 64 + lane * 2);
                float2 a = __half22float2(*(const __half2*)&p);
                acc.x += wj * a.x; acc.y += wj * a.y;
            }
        }
        for (; e < m; e++) {
            int sj = cols[e];
            float wj = rsqrtf((float)(g_cnt[sj] + 1));
            uint32_t p = *(const uint32_t*)(xw + (size_t)sj * 64 + lane * 2);
            float2 a = __half22float2(*(const __half2*)&p);
            acc.x += wj * a.x; acc.y += wj * a.y;
        }
        acc.x *= di; acc.y *= di;
        *(float2*)(out + (size_t)node * 64 + lane * 2) = acc;
    }
    sv[wid][lane * 2 + 0] = acc.x;
    sv[wid][lane * 2 + 1] = acc.y;
    __syncthreads();
    int t = threadIdx.x;
    if (t < 64) {
        float s = 0.f, q = 0.f;
#pragma unroll
        for (int w2 = 0; w2 < 32; w2++) {
            float v = sv[w2][t];
            s += v; q += v * v;
        }
        atomicAdd(&psum[t], s);
        atomicAdd(&psumsq[t], q);
    }
}

// fp16 tensor-core GEMM, 256 threads / 8 warps (2m x 4n), warp tile 64 x (NBLK/4).
// Pipeline prologue: W0 copies + A staging issued FIRST, then ONE commit + wait
// (bundles the A cp.asyncs into the committed group — fixes the R10 ordering race).
template <int NBLK, int NITER, int KCH, int INF16, int MODE, int STATS, int OUTF16>
__global__ __launch_bounds__(256, 2)
void mma_gemm_kernel(const void* __restrict__ Av,
                     const uint8_t* __restrict__ wimg,
                     void* __restrict__ Cv,
                     const float* __restrict__ gamma,
                     const float* __restrict__ beta,
                     const float* __restrict__ psum_in,
                     const float* __restrict__ psumsq_in,
                     float* __restrict__ psum_out,
                     float* __restrict__ psumsq_out, int M) {
    extern __shared__ char dsm[];
    char* sm = (char*)(((uintptr_t)dsm + 1023) & ~(uintptr_t)1023);
    uint32_t sbase = smem_to_u32(sm);

    constexpr int WN = NBLK / 4;
    constexpr int NT = WN / 8;
    constexpr int NG = NT / 2;
    constexpr int K = KCH * 128;
    constexpr int N = NITER * NBLK;
    constexpr int TOTAL = NITER * KCH;
    constexpr int wchunk = 128 * NBLK * 2;
    const int OFF_A = 0;
    const int OFF_W = 32768;

    __shared__ float s_scale[256], s_shift[256];

    const float* Af = (const float*)Av;
    const __half* Ah = (const __half*)Av;

    int tid = threadIdx.x;
    int wid = tid >> 5, lane = tid & 31;
    int wm = (wid >> 2) * 64;
    int wn = (wid & 3) * WN;
    int mrow0 = blockIdx.y * 128;

    if (MODE == 1) {
        if (tid < K) {
            float invn = 1.f / (float)M;
            float mv = psum_in[tid] * invn;
            float var = psumsq_in[tid] * invn - mv * mv;
            float sc = gamma[tid] * rsqrtf(var + EPS);
            s_scale[tid] = sc;
            s_shift[tid] = beta[tid] - mv * sc;
        }
        __syncthreads();
    }

    int lrow = (lane & 7) + ((lane & 8) ? 8 : 0);
    int lsel = (lane >> 4) & 1;
    int arow[4];
#pragma unroll
    for (int mi = 0; mi < 4; mi++) arow[mi] = wm + mi * 16 + lrow;
    int kx = lane & 7;
    int g4 = lane >> 2, tig = lane & 3;

    auto stage_A = [&](int c) {
#pragma unroll
        for (int it = 0; it < 8; it++) {
            int u = tid + it * 256;
            int m = u >> 4, kc8 = u & 15;
            int row = mrow0 + m;
            uint32_t dst = sbase + OFF_A +
                           (uint32_t)(m * 256 + ((kc8 ^ (m & 7)) << 4));
            if (INF16 && MODE == 0) {
                if (row < M) cp16(dst, Ah + (size_t)row * K + c * 128 + kc8 * 8);
                else *(uint4*)(sm + (dst - sbase)) = make_uint4(0, 0, 0, 0);
            } else {
                uint4 o;
                if (row < M) {
                    float v[8];
                    if (INF16) {
                        uint4 p4 = *(const uint4*)(Ah + (size_t)row * K + c * 128 + kc8 * 8);
                        float2 t0 = __half22float2(*(const __half2*)&p4.x);
                        float2 t1 = __half22float2(*(const __half2*)&p4.y);
                        float2 t2 = __half22float2(*(const __half2*)&p4.z);
                        float2 t3 = __half22float2(*(const __half2*)&p4.w);
                        v[0] = t0.x; v[1] = t0.y; v[2] = t1.x; v[3] = t1.y;
                        v[4] = t2.x; v[5] = t2.y; v[6] = t3.x; v[7] = t3.y;
                    } else {
                        float4 f0 = *(const float4*)(Af + (size_t)row * K + c * 128 + kc8 * 8);
                        float4 f1 = *(const float4*)(Af + (size_t)row * K + c * 128 + kc8 * 8 + 4);
                        v[0] = f0.x; v[1] = f0.y; v[2] = f0.z; v[3] = f0.w;
                        v[4] = f1.x; v[5] = f1.y; v[6] = f1.z; v[7] = f1.w;
                    }
                    if (MODE == 1) {
#pragma unroll
                        for (int j = 0; j < 8; j++) {
                            int kg = c * 128 + kc8 * 8 + j;
                            float y = v[j] * s_scale[kg] + s_shift[kg];
                            v[j] = 1.f / (1.f + __expf(-y));
                        }
                    }
                    *(__half2*)&o.x = __floats2half2_rn(v[0], v[1]);
                    *(__half2*)&o.y = __floats2half2_rn(v[2], v[3]);
                    *(__half2*)&o.z = __floats2half2_rn(v[4], v[5]);
                    *(__half2*)&o.w = __floats2half2_rn(v[6], v[7]);
                } else {
                    o = make_uint4(0, 0, 0, 0);
                }
                *(uint4*)(sm + (dst - sbase)) = o;
            }
        }
    };

    auto issue_W = [&](int t, int buf) {
        int nb_ = t / KCH, c_ = t % KCH;
        const uint8_t* src = wimg +
            ((size_t)(blockIdx.x * NITER + nb_) * KCH + c_) * (size_t)wchunk;
#pragma unroll
        for (int i = 0; i < wchunk / (256 * 16); i++) {
            int off = (tid + i * 256) * 16;
            cp16(sbase + OFF_W + buf * wchunk + off, src + off);
        }
    };

    // ---- prologue: issue W0 and A, then commit+wait ONE group (race fix) ----
    issue_W(0, 0);
    stage_A(0);
    CP_COMMIT();
    CP_WAIT0();
    __syncthreads();
    if (TOTAL > 1) {
        issue_W(1, 1);
        CP_COMMIT();
    }

    for (int nb = 0; nb < NITER; nb++) {
        float acc[4][NT][4];
#pragma unroll
        for (int mi = 0; mi < 4; mi++)
#pragma unroll
            for (int nj = 0; nj < NT; nj++)
#pragma unroll
                for (int q = 0; q < 4; q++) acc[mi][nj][q] = 0.f;

        for (int c = 0; c < KCH; c++) {
            int t = nb * KCH + c;
            if (t > 0) {
                __syncthreads();
                if (KCH == 2 && c == 1) stage_A(1);
                CP_WAIT0();
                __syncthreads();
            }
            int buf = t & 1;
#pragma unroll
            for (int s = 0; s < 8; s++) {
                uint32_t a[4][4];
                int achunk = s * 2 + lsel;
#pragma unroll
                for (int mi = 0; mi < 4; mi++) {
                    uint32_t aoff = (uint32_t)(arow[mi] * 256 +
                                               ((achunk ^ (arow[mi] & 7)) << 4));
                    ldmx4(a[mi], sbase + OFF_A + aoff);
                }
                uint32_t wr[NT * 2];
                int kr = s * 16 + lrow;
#pragma unroll
                for (int grp = 0; grp < NG; grp++) {
                    int cn = (wn + grp * 16 + lsel * 8) >> 3;
                    uint32_t woff = (uint32_t)(kr * (NBLK * 2) + ((cn ^ kx) << 4));
                    ldmx4t(&wr[grp * 4], sbase + OFF_W + buf * wchunk + woff);
                }
#pragma unroll
                for (int mi = 0; mi < 4; mi++)
#pragma unroll
                    for (int nj = 0; nj < NT; nj++)
                        mma_f16(acc[mi][nj], a[mi], &wr[nj * 2]);
            }
        }

        int bcol = (blockIdx.x * NITER + nb) * NBLK;
#pragma unroll
        for (int mi = 0; mi < 4; mi++) {
            int row = mrow0 + wm + mi * 16 + g4;
#pragma unroll
            for (int nj = 0; nj < NT; nj++) {
                int col = bcol + wn + nj * 8 + tig * 2;
                if (OUTF16) {
                    __half* Ch = (__half*)Cv;
                    if (row < M)
                        *(__half2*)(Ch + (size_t)row * N + col) =
                            __floats2half2_rn(acc[mi][nj][0], acc[mi][nj][1]);
                    if (row + 8 < M)
                        *(__half2*)(Ch + (size_t)(row + 8) * N + col) =
                            __floats2half2_rn(acc[mi][nj][2], acc[mi][nj][3]);
                } else {
                    float* Cf = (float*)Cv;
                    if (row < M)
                        *(float2*)(Cf + (size_t)row * N + col) =
                            make_float2(acc[mi][nj][0], acc[mi][nj][1]);
                    if (row + 8 < M)
                        *(float2*)(Cf + (size_t)(row + 8) * N + col) =
                            make_float2(acc[mi][nj][2], acc[mi][nj][3]);
                }
            }
        }

        if (STATS) {
            __shared__ float sp_s[8][WN], sp_q[8][WN];
#pragma unroll
            for (int nj = 0; nj < NT; nj++) {
                float c0 = 0.f, c1 = 0.f, q0 = 0.f, q1 = 0.f;
#pragma unroll
                for (int mi = 0; mi < 4; mi++) {
                    c0 += acc[mi][nj][0] + acc[mi][nj][2];
                    c1 += acc[mi][nj][1] + acc[mi][nj][3];
                    q0 += acc[mi][nj][0] * acc[mi][nj][0] +
                          acc[mi][nj][2] * acc[mi][nj][2];
                    q1 += acc[mi][nj][1] * acc[mi][nj][1] +
                          acc[mi][nj][3] * acc[mi][nj][3];
                }
#pragma unroll
                for (int o = 4; o < 32; o <<= 1) {
                    c0 += __shfl_xor_sync(0xffffffffu, c0, o);
                    c1 += __shfl_xor_sync(0xffffffffu, c1, o);
                    q0 += __shfl_xor_sync(0xffffffffu, q0, o);
                    q1 += __shfl_xor_sync(0xffffffffu, q1, o);
                }
                if (lane < 4) {
                    sp_s[wid][nj * 8 + lane * 2 + 0] = c0;
                    sp_s[wid][nj * 8 + lane * 2 + 1] = c1;
                    sp_q[wid][nj * 8 + lane * 2 + 0] = q0;
                    sp_q[wid][nj * 8 + lane * 2 + 1] = q1;
                }
            }
            __syncthreads();
            if (tid < NBLK) {
                int p = tid / WN, lc = tid % WN;
                float s = sp_s[p][lc] + sp_s[p + 4][lc];
                float q = sp_q[p][lc] + sp_q[p + 4][lc];
                atomicAdd(&psum_out[bcol + tid], s);
                atomicAdd(&psumsq_out[bcol + tid], q);
            }
            __syncthreads();
        }
    }
}

__global__ void decode_kernel(const float* __restrict__ z,
                              const int* __restrict__ pe,
                              const int* __restrict__ ne,
                              const float* __restrict__ gamma,
                              const float* __restrict__ beta,
                              const float* __restrict__ psum,
                              const float* __restrict__ psumsq,
                              float* __restrict__ out, int P, int Q, int n) {
    __shared__ float s_sc[64], s_sh[64];
    int tid = threadIdx.x;
    if (tid < 64) {
        float invn = 1.f / (float)n;
        float m = psum[tid] * invn;
        float var = psumsq[tid] * invn - m * m;
        float sc = gamma[tid] * rsqrtf(var + EPS);
        s_sc[tid] = sc;
        s_sh[tid] = beta[tid] - m * sc;
    }
    __syncthreads();
    int idx = blockIdx.x * blockDim.x + tid;
    int eg = idx >> 4;
    int l = idx & 15;
    if (eg >= P + Q) return;
    int a, b;
    if (eg < P) { a = pe[eg];     b = pe[P + eg]; }
    else        { int e = eg - P; a = ne[e]; b = ne[Q + e]; }
    float4 sc = ((const float4*)s_sc)[l];
    float4 sh = ((const float4*)s_sh)[l];
    float4 xa = ((const float4*)(z + (size_t)a * 64))[l];
    float4 xb = ((const float4*)(z + (size_t)b * 64))[l];
    xa.x = xa.x * sc.x + sh.x; xa.y = xa.y * sc.y + sh.y;
    xa.z = xa.z * sc.z + sh.z; xa.w = xa.w * sc.w + sh.w;
    xb.x = xb.x * sc.x + sh.x; xb.y = xb.y * sc.y + sh.y;
    xb.z = xb.z * sc.z + sh.z; xb.w = xb.w * sc.w + sh.w;
    float s = xa.x * xb.x + xa.y * xb.y + xa.z * xb.z + xa.w * xb.w;
    s += __shfl_xor_sync(0xffffffffu, s, 8);
    s += __shfl_xor_sync(0xffffffffu, s, 4);
    s += __shfl_xor_sync(0xffffffffu, s, 2);
    s += __shfl_xor_sync(0xffffffffu, s, 1);
    if (l == 0) out[eg] = s;
}

extern "C" void kernel_launch(void* const* d_in, const int* in_sizes, int n_in,
                              void* d_out, int out_size) {
    const float* x  = (const float*)d_in[0];
    const int*   ei = (const int*)d_in[1];
    const int*   pe = (const int*)d_in[2];
    const int*   ne = (const int*)d_in[3];
    const float* W1 = (const float*)d_in[4];
    const float* g1 = (const float*)d_in[6];
    const float* be1= (const float*)d_in[7];
    const float* W2 = (const float*)d_in[8];
    const float* g2 = (const float*)d_in[10];
    const float* be2= (const float*)d_in[11];
    const float* W3 = (const float*)d_in[12];
    const float* g3 = (const float*)d_in[14];
    const float* be3= (const float*)d_in[15];

    int N = in_sizes[0] / 128;
    int E = in_sizes[1] / 2;
    int P = in_sizes[2] / 2;
    int Q = in_sizes[3] / 2;

    float* bufA; float* bufB; uint8_t* wimg; float* sum; float* sumsq;
    cudaGetSymbolAddress((void**)&bufA, g_bufA);
    cudaGetSymbolAddress((void**)&bufB, g_bufB);
    cudaGetSymbolAddress((void**)&wimg, g_wimg);
    cudaGetSymbolAddress((void**)&sum, g_sum);
    cudaGetSymbolAddress((void**)&sumsq, g_sumsq);

    __half* x16 = (__half*)bufA;
    __half* a1  = (__half*)(bufA + 6400000);
    __half* h1  = (__half*)bufB;
    __half* h2  = (__half*)(bufB + 12800000);
    float*  b2  = bufA;
    __half* h3  = (__half*)(bufB + 19200000);
    float*  z   = bufB;

    float* out = (float*)d_out;

    int nb = (N + 255) / 256;
    int eb4 = (E / 4 + 255) / 256;
    int xb = (N * 16 + 255) / 256;
    int aggB256 = (N * 32 + 255) / 256;
    int aggB1024 = (N + 31) / 32;
    int mtiles = (N + 127) / 128;

    const int SMEM_L1 = 1024 + 32768 + 2 * 32768;
    const int SMEM_L2 = 1024 + 32768 + 2 * 32768;
    const int SMEM_L3 = 1024 + 32768 + 16384;
    cudaFuncSetAttribute((const void*)mma_gemm_kernel<128, 2, 1, 1, 0, 1, 1>,
                         cudaFuncAttributeMaxDynamicSharedMemorySize, SMEM_L1);
    cudaFuncSetAttribute((const void*)mma_gemm_kernel<128, 1, 2, 1, 1, 0, 1>,
                         cudaFuncAttributeMaxDynamicSharedMemorySize, SMEM_L2);
    cudaFuncSetAttribute((const void*)mma_gemm_kernel<64, 1, 1, 0, 1, 0, 1>,
                         cudaFuncAttributeMaxDynamicSharedMemorySize, SMEM_L3);

    prep_kernel<<<nb + 288, 256>>>(W1, W2, W3, wimg, N, nb);
    combo_kernel<<<eb4 + xb, 256>>>(ei, ei + E, E, eb4, x, x16, N * 16);
    agg128_f16_kernel<<<aggB256, 256>>>(x16, a1, N);

    mma_gemm_kernel<128, 2, 1, 1, 0, 1, 1><<<dim3(1, mtiles), 256, SMEM_L1>>>(
        a1, wimg + 0, h1, nullptr, nullptr, nullptr, nullptr,
        sum, sumsq, N);

    mma_gemm_kernel<128, 1, 2, 1, 1, 0, 1><<<dim3(1, mtiles), 256, SMEM_L2>>>(
        h1, wimg + 65536, h2, g1, be1, sum, sumsq,
        nullptr, nullptr, N);
    agg128_stats_f16_kernel<<<aggB1024, 1024>>>(h2, b2, sum + 256, sumsq + 256, N);

    mma_gemm_kernel<64, 1, 1, 0, 1, 0, 1><<<dim3(1, mtiles), 256, SMEM_L3>>>(
        b2, wimg + 131072, h3, g2, be2, sum + 256, sumsq + 256,
        nullptr, nullptr, N);
    agg64_stats_f16_kernel<<<aggB1024, 1024>>>(h3, z, sum + 384, sumsq + 384, N);

    {
        int tot = (P + Q) * 16;
        decode_kernel<<<(tot + 255) / 256, 256>>>(
            z, pe, ne, g3, be3, sum + 384, sumsq + 384, out, P, Q, N);
    }
}

// round 17
// speedup vs baseline: 1.3583x; 1.1334x over previous
#include <cuda_runtime.h>
#include <cuda_bf16.h>
#include <cuda_fp16.h>
#include <math.h>
#include <stdint.h>

#define MAXN 100000
#define MAXE 1600000
#define EPS 1e-5f
#define CAP 96

__device__ float g_bufA[MAXN * 128];
__device__ float g_bufB[MAXN * 256];
__device__ int   g_cnt[MAXN];
__device__ int   g_colpad[MAXN * CAP];
__device__ float g_sum[448];
__device__ float g_sumsq[448];
__device__ uint8_t g_wimg[147456];

__device__ __forceinline__ uint32_t smem_to_u32(const void* smem_ptr) {
    uint32_t addr;
    asm("{ .reg .u64 tmp; cvta.to.shared.u64 tmp, %1; cvt.u32.u64 %0, tmp; }"
        : "=r"(addr) : "l"(smem_ptr));
    return addr;
}

__device__ __forceinline__ void ldmx4(uint32_t* r, uint32_t addr) {
    asm volatile(
        "ldmatrix.sync.aligned.m8n8.x4.shared.b16 {%0,%1,%2,%3}, [%4];"
        : "=r"(r[0]), "=r"(r[1]), "=r"(r[2]), "=r"(r[3]) : "r"(addr));
}

__device__ __forceinline__ void ldmx4t(uint32_t* r, uint32_t addr) {
    asm volatile(
        "ldmatrix.sync.aligned.m8n8.x4.trans.shared.b16 {%0,%1,%2,%3}, [%4];"
        : "=r"(r[0]), "=r"(r[1]), "=r"(r[2]), "=r"(r[3]) : "r"(addr));
}

__device__ __forceinline__ void mma_f16(float* c, const uint32_t* a,
                                        const uint32_t* b) {
    asm volatile(
        "mma.sync.aligned.m16n8k16.row.col.f32.f16.f16.f32 "
        "{%0,%1,%2,%3}, {%4,%5,%6,%7}, {%8,%9}, {%0,%1,%2,%3};"
        : "+f"(c[0]), "+f"(c[1]), "+f"(c[2]), "+f"(c[3])
        : "r"(a[0]), "r"(a[1]), "r"(a[2]), "r"(a[3]), "r"(b[0]), "r"(b[1]));
}

__device__ __forceinline__ void cp16(uint32_t dst, const void* src) {
    asm volatile("cp.async.cg.shared.global [%0], [%1], 16;"
                 :: "r"(dst), "l"(src) : "memory");
}
#define CP_COMMIT() asm volatile("cp.async.commit_group;" ::: "memory")
#define CP_WAIT0()  asm volatile("cp.async.wait_group 0;" ::: "memory")

// sigmoid via single HW MUFU op: sigma(y) = 0.5*tanh(0.5*y) + 0.5
__device__ __forceinline__ float sigmoid_fast(float y) {
    float t;
    asm("tanh.approx.f32 %0, %1;" : "=f"(t) : "f"(y * 0.5f));
    return fmaf(t, 0.5f, 0.5f);
}

__device__ __forceinline__ void wprep_one(const float* __restrict__ W,
                                          uint8_t* __restrict__ img,
                                          int idx, int K, int N, int NBLK) {
    int k = idx / N, n = idx % N;
    __half h = __float2half_rn(W[idx]);
    int nblk = n / NBLK, nloc = n % NBLK;
    uint32_t addr = (uint32_t)nblk * (uint32_t)(K * NBLK * 2) +
                    (uint32_t)k * (uint32_t)(NBLK * 2) +
                    (uint32_t)(((nloc >> 3) ^ (k & 7)) << 4) +
                    (uint32_t)((nloc * 2) & 15);
    *(__half*)(img + addr) = h;
}

__global__ void prep_kernel(const float* __restrict__ W1,
                            const float* __restrict__ W2,
                            const float* __restrict__ W3,
                            uint8_t* __restrict__ wimg, int n, int nb) {
    int b = blockIdx.x, t = threadIdx.x;
    if (b < nb) {
        int i = b * 256 + t;
        if (i < n) g_cnt[i] = 0;
        if (b == 0) { g_sum[t] = 0.f; g_sumsq[t] = 0.f; }
        if (b == 1 && t < 192) { g_sum[256 + t] = 0.f; g_sumsq[256 + t] = 0.f; }
    } else if (b < nb + 128) {
        int idx = (b - nb) * 256 + t;
        wprep_one(W1, wimg + 0, idx, 128, 256, 128);
    } else if (b < nb + 256) {
        int idx = (b - nb - 128) * 256 + t;
        wprep_one(W2, wimg + 65536, idx, 256, 128, 128);
    } else {
        int idx = (b - nb - 256) * 256 + t;
        if (idx < 8192)
            wprep_one(W3, wimg + 131072, idx, 128, 64, 64);
    }
}

__global__ __launch_bounds__(256)
void combo_kernel(const int* __restrict__ src, const int* __restrict__ dst,
                  int E, int eb4,
                  const float* __restrict__ x, __half* __restrict__ x16,
                  int ntot16) {
    int b = blockIdx.x, t = threadIdx.x;
    if (b < eb4) {
        int base = (b * 256 + t) * 4;
        if (base < E) {
            int4 s4 = *(const int4*)(src + base);
            int4 d4 = *(const int4*)(dst + base);
            int ds[4] = {d4.x, d4.y, d4.z, d4.w};
            int ss[4] = {s4.x, s4.y, s4.z, s4.w};
#pragma unroll
            for (int j = 0; j < 4; j++) {
                int p = atomicAdd(&g_cnt[ds[j]], 1);
                if (p < CAP) g_colpad[(size_t)ds[j] * CAP + p] = ss[j];
            }
        }
    } else {
        int xi = (b - eb4) * 256 + t;
        if (xi < ntot16) {
            int base = xi * 8;
            float4 f0 = *(const float4*)(x + base);
            float4 f1 = *(const float4*)(x + base + 4);
            uint4 o;
            *(__half2*)&o.x = __floats2half2_rn(f0.x, f0.y);
            *(__half2*)&o.y = __floats2half2_rn(f0.z, f0.w);
            *(__half2*)&o.z = __floats2half2_rn(f1.x, f1.y);
            *(__half2*)&o.w = __floats2half2_rn(f1.z, f1.w);
            *(uint4*)(x16 + base) = o;
        }
    }
}

__global__ __launch_bounds__(256)
void agg128_f16_kernel(const __half* __restrict__ xw,
                       __half* __restrict__ out, int n) {
    int node = (blockIdx.x * blockDim.x + threadIdx.x) >> 5;
    int lane = threadIdx.x & 31;
    if (node >= n) return;
    int cd = g_cnt[node];
    float di = rsqrtf((float)(cd + 1));
    float4 acc;
    {
        uint2 p = *(const uint2*)(xw + (size_t)node * 128 + lane * 4);
        float2 a = __half22float2(*(const __half2*)&p.x);
        float2 b = __half22float2(*(const __half2*)&p.y);
        acc.x = di * a.x; acc.y = di * a.y; acc.z = di * b.x; acc.w = di * b.y;
    }
    int m = cd < CAP ? cd : CAP;
    const int* cols = g_colpad + (size_t)node * CAP;
    int e = 0;
    for (; e + 8 <= m; e += 8) {
        int s = 0; float w = 0.f;
        if (lane < 8) {
            s = cols[e + lane];
            w = rsqrtf((float)(g_cnt[s] + 1));
        }
#pragma unroll
        for (int j = 0; j < 8; j++) {
            int sj = __shfl_sync(0xffffffffu, s, j);
            float wj = __shfl_sync(0xffffffffu, w, j);
            uint2 p = *(const uint2*)(xw + (size_t)sj * 128 + lane * 4);
            float2 a = __half22float2(*(const __half2*)&p.x);
            float2 b = __half22float2(*(const __half2*)&p.y);
            acc.x += wj * a.x; acc.y += wj * a.y;
            acc.z += wj * b.x; acc.w += wj * b.y;
        }
    }
    for (; e < m; e++) {
        int sj = cols[e];
        float wj = rsqrtf((float)(g_cnt[sj] + 1));
        uint2 p = *(const uint2*)(xw + (size_t)sj * 128 + lane * 4);
        float2 a = __half22float2(*(const __half2*)&p.x);
        float2 b = __half22float2(*(const __half2*)&p.y);
        acc.x += wj * a.x; acc.y += wj * a.y;
        acc.z += wj * b.x; acc.w += wj * b.y;
    }
    uint2 o;
    *(__half2*)&o.x = __floats2half2_rn(acc.x * di, acc.y * di);
    *(__half2*)&o.y = __floats2half2_rn(acc.z * di, acc.w * di);
    *(uint2*)(out + (size_t)node * 128 + lane * 4) = o;
}

// agg layer 2: fp16 in, fp16 out, fused BN stats (fp32 accumulation)
__global__ __launch_bounds__(1024)
void agg128_stats_f16_kernel(const __half* __restrict__ xw,
                             __half* __restrict__ out,
                             float* __restrict__ psum,
                             float* __restrict__ psumsq, int n) {
    __shared__ float sv[32][128];
    int wid = threadIdx.x >> 5, lane = threadIdx.x & 31;
    int node = blockIdx.x * 32 + wid;
    float4 acc = make_float4(0.f, 0.f, 0.f, 0.f);
    if (node < n) {
        int cd = g_cnt[node];
        float di = rsqrtf((float)(cd + 1));
        {
            uint2 p = *(const uint2*)(xw + (size_t)node * 128 + lane * 4);
            float2 a = __half22float2(*(const __half2*)&p.x);
            float2 b = __half22float2(*(const __half2*)&p.y);
            acc.x = di * a.x; acc.y = di * a.y;
            acc.z = di * b.x; acc.w = di * b.y;
        }
        int m = cd < CAP ? cd : CAP;
        const int* cols = g_colpad + (size_t)node * CAP;
        int e = 0;
        for (; e + 8 <= m; e += 8) {
            int s = 0; float w = 0.f;
            if (lane < 8) {
                s = cols[e + lane];
                w = rsqrtf((float)(g_cnt[s] + 1));
            }
#pragma unroll
            for (int j = 0; j < 8; j++) {
                int sj = __shfl_sync(0xffffffffu, s, j);
                float wj = __shfl_sync(0xffffffffu, w, j);
                uint2 p = *(const uint2*)(xw + (size_t)sj * 128 + lane * 4);
                float2 a = __half22float2(*(const __half2*)&p.x);
                float2 b = __half22float2(*(const __half2*)&p.y);
                acc.x += wj * a.x; acc.y += wj * a.y;
                acc.z += wj * b.x; acc.w += wj * b.y;
            }
        }
        for (; e < m; e++) {
            int sj = cols[e];
            float wj = rsqrtf((float)(g_cnt[sj] + 1));
            uint2 p = *(const uint2*)(xw + (size_t)sj * 128 + lane * 4);
            float2 a = __half22float2(*(const __half2*)&p.x);
            float2 b = __half22float2(*(const __half2*)&p.y);
            acc.x += wj * a.x; acc.y += wj * a.y;
            acc.z += wj * b.x; acc.w += wj * b.y;
        }
        acc.x *= di; acc.y *= di; acc.z *= di; acc.w *= di;
        uint2 o;
        *(__half2*)&o.x = __floats2half2_rn(acc.x, acc.y);
        *(__half2*)&o.y = __floats2half2_rn(acc.z, acc.w);
        *(uint2*)(out + (size_t)node * 128 + lane * 4) = o;
    }
    sv[wid][lane * 4 + 0] = acc.x;
    sv[wid][lane * 4 + 1] = acc.y;
    sv[wid][lane * 4 + 2] = acc.z;
    sv[wid][lane * 4 + 3] = acc.w;
    __syncthreads();
    int t = threadIdx.x;
    if (t < 128) {
        float s = 0.f, q = 0.f;
#pragma unroll
        for (int w2 = 0; w2 < 32; w2++) {
            float v = sv[w2][t];
            s += v; q += v * v;
        }
        atomicAdd(&psum[t], s);
        atomicAdd(&psumsq[t], q);
    }
}

__global__ __launch_bounds__(1024)
void agg64_stats_f16_kernel(const __half* __restrict__ xw,
                            float* __restrict__ out,
                            float* __restrict__ psum,
                            float* __restrict__ psumsq, int n) {
    __shared__ float sv[32][64];
    int wid = threadIdx.x >> 5, lane = threadIdx.x & 31;
    int node = blockIdx.x * 32 + wid;
    float2 acc = make_float2(0.f, 0.f);
    if (node < n) {
        int cd = g_cnt[node];
        float di = rsqrtf((float)(cd + 1));
        {
            uint32_t p = *(const uint32_t*)(xw + (size_t)node * 64 + lane * 2);
            float2 a = __half22float2(*(const __half2*)&p);
            acc.x = di * a.x; acc.y = di * a.y;
        }
        int m = cd < CAP ? cd : CAP;
        const int* cols = g_colpad + (size_t)node * CAP;
        int e = 0;
        for (; e + 8 <= m; e += 8) {
            int s = 0; float w = 0.f;
            if (lane < 8) {
                s = cols[e + lane];
                w = rsqrtf((float)(g_cnt[s] + 1));
            }
#pragma unroll
            for (int j = 0; j < 8; j++) {
                int sj = __shfl_sync(0xffffffffu, s, j);
                float wj = __shfl_sync(0xffffffffu, w, j);
                uint32_t p = *(const uint32_t*)(xw + (size_t)sj * 64 + lane * 2);
                float2 a = __half22float2(*(const __half2*)&p);
                acc.x += wj * a.x; acc.y += wj * a.y;
            }
        }
        for (; e < m; e++) {
            int sj = cols[e];
            float wj = rsqrtf((float)(g_cnt[sj] + 1));
            uint32_t p = *(const uint32_t*)(xw + (size_t)sj * 64 + lane * 2);
            float2 a = __half22float2(*(const __half2*)&p);
            acc.x += wj * a.x; acc.y += wj * a.y;
        }
        acc.x *= di; acc.y *= di;
        *(float2*)(out + (size_t)node * 64 + lane * 2) = acc;
    }
    sv[wid][lane * 2 + 0] = acc.x;
    sv[wid][lane * 2 + 1] = acc.y;
    __syncthreads();
    int t = threadIdx.x;
    if (t < 64) {
        float s = 0.f, q = 0.f;
#pragma unroll
        for (int w2 = 0; w2 < 32; w2++) {
            float v = sv[w2][t];
            s += v; q += v * v;
        }
        atomicAdd(&psum[t], s);
        atomicAdd(&psumsq[t], q);
    }
}

// fp16 tensor-core GEMM, 256 threads / 8 warps (2m x 4n), warp tile 64 x (NBLK/4).
// Prologue: W0 + A issued, then ONE commit + wait (race-fixed ordering).
template <int NBLK, int NITER, int KCH, int INF16, int MODE, int STATS, int OUTF16>
__global__ __launch_bounds__(256, 2)
void mma_gemm_kernel(const void* __restrict__ Av,
                     const uint8_t* __restrict__ wimg,
                     void* __restrict__ Cv,
                     const float* __restrict__ gamma,
                     const float* __restrict__ beta,
                     const float* __restrict__ psum_in,
                     const float* __restrict__ psumsq_in,
                     float* __restrict__ psum_out,
                     float* __restrict__ psumsq_out, int M) {
    extern __shared__ char dsm[];
    char* sm = (char*)(((uintptr_t)dsm + 1023) & ~(uintptr_t)1023);
    uint32_t sbase = smem_to_u32(sm);

    constexpr int WN = NBLK / 4;
    constexpr int NT = WN / 8;
    constexpr int NG = NT / 2;
    constexpr int K = KCH * 128;
    constexpr int N = NITER * NBLK;
    constexpr int TOTAL = NITER * KCH;
    constexpr int wchunk = 128 * NBLK * 2;
    const int OFF_A = 0;
    const int OFF_W = 32768;

    __shared__ float s_scale[256], s_shift[256];

    const float* Af = (const float*)Av;
    const __half* Ah = (const __half*)Av;

    int tid = threadIdx.x;
    int wid = tid >> 5, lane = tid & 31;
    int wm = (wid >> 2) * 64;
    int wn = (wid & 3) * WN;
    int mrow0 = blockIdx.y * 128;

    if (MODE == 1) {
        if (tid < K) {
            float invn = 1.f / (float)M;
            float mv = psum_in[tid] * invn;
            float var = psumsq_in[tid] * invn - mv * mv;
            float sc = gamma[tid] * rsqrtf(var + EPS);
            s_scale[tid] = sc;
            s_shift[tid] = beta[tid] - mv * sc;
        }
        __syncthreads();
    }

    int lrow = (lane & 7) + ((lane & 8) ? 8 : 0);
    int lsel = (lane >> 4) & 1;
    int arow[4];
#pragma unroll
    for (int mi = 0; mi < 4; mi++) arow[mi] = wm + mi * 16 + lrow;
    int kx = lane & 7;
    int g4 = lane >> 2, tig = lane & 3;

    auto stage_A = [&](int c) {
#pragma unroll
        for (int it = 0; it < 8; it++) {
            int u = tid + it * 256;
            int m = u >> 4, kc8 = u & 15;
            int row = mrow0 + m;
            uint32_t dst = sbase + OFF_A +
                           (uint32_t)(m * 256 + ((kc8 ^ (m & 7)) << 4));
            if (INF16 && MODE == 0) {
                if (row < M) cp16(dst, Ah + (size_t)row * K + c * 128 + kc8 * 8);
                else *(uint4*)(sm + (dst - sbase)) = make_uint4(0, 0, 0, 0);
            } else {
                uint4 o;
                if (row < M) {
                    float v[8];
                    if (INF16) {
                        uint4 p4 = *(const uint4*)(Ah + (size_t)row * K + c * 128 + kc8 * 8);
                        float2 t0 = __half22float2(*(const __half2*)&p4.x);
                        float2 t1 = __half22float2(*(const __half2*)&p4.y);
                        float2 t2 = __half22float2(*(const __half2*)&p4.z);
                        float2 t3 = __half22float2(*(const __half2*)&p4.w);
                        v[0] = t0.x; v[1] = t0.y; v[2] = t1.x; v[3] = t1.y;
                        v[4] = t2.x; v[5] = t2.y; v[6] = t3.x; v[7] = t3.y;
                    } else {
                        float4 f0 = *(const float4*)(Af + (size_t)row * K + c * 128 + kc8 * 8);
                        float4 f1 = *(const float4*)(Af + (size_t)row * K + c * 128 + kc8 * 8 + 4);
                        v[0] = f0.x; v[1] = f0.y; v[2] = f0.z; v[3] = f0.w;
                        v[4] = f1.x; v[5] = f1.y; v[6] = f1.z; v[7] = f1.w;
                    }
                    if (MODE == 1) {
#pragma unroll
                        for (int j = 0; j < 8; j++) {
                            int kg = c * 128 + kc8 * 8 + j;
                            float y = v[j] * s_scale[kg] + s_shift[kg];
                            v[j] = sigmoid_fast(y);
                        }
                    }
                    *(__half2*)&o.x = __floats2half2_rn(v[0], v[1]);
                    *(__half2*)&o.y = __floats2half2_rn(v[2], v[3]);
                    *(__half2*)&o.z = __floats2half2_rn(v[4], v[5]);
                    *(__half2*)&o.w = __floats2half2_rn(v[6], v[7]);
                } else {
                    o = make_uint4(0, 0, 0, 0);
                }
                *(uint4*)(sm + (dst - sbase)) = o;
            }
        }
    };

    auto issue_W = [&](int t, int buf) {
        int nb_ = t / KCH, c_ = t % KCH;
        const uint8_t* src = wimg +
            ((size_t)(blockIdx.x * NITER + nb_) * KCH + c_) * (size_t)wchunk;
#pragma unroll
        for (int i = 0; i < wchunk / (256 * 16); i++) {
            int off = (tid + i * 256) * 16;
            cp16(sbase + OFF_W + buf * wchunk + off, src + off);
        }
    };

    // ---- prologue: issue W0 and A, then commit+wait ONE group (race fix) ----
    issue_W(0, 0);
    stage_A(0);
    CP_COMMIT();
    CP_WAIT0();
    __syncthreads();
    if (TOTAL > 1) {
        issue_W(1, 1);
        CP_COMMIT();
    }

    for (int nb = 0; nb < NITER; nb++) {
        float acc[4][NT][4];
#pragma unroll
        for (int mi = 0; mi < 4; mi++)
#pragma unroll
            for (int nj = 0; nj < NT; nj++)
#pragma unroll
                for (int q = 0; q < 4; q++) acc[mi][nj][q] = 0.f;

        for (int c = 0; c < KCH; c++) {
            int t = nb * KCH + c;
            if (t > 0) {
                __syncthreads();
                if (KCH == 2 && c == 1) stage_A(1);
                CP_WAIT0();
                __syncthreads();
            }
            int buf = t & 1;
#pragma unroll
            for (int s = 0; s < 8; s++) {
                uint32_t a[4][4];
                int achunk = s * 2 + lsel;
#pragma unroll
                for (int mi = 0; mi < 4; mi++) {
                    uint32_t aoff = (uint32_t)(arow[mi] * 256 +
                                               ((achunk ^ (arow[mi] & 7)) << 4));
                    ldmx4(a[mi], sbase + OFF_A + aoff);
                }
                uint32_t wr[NT * 2];
                int kr = s * 16 + lrow;
#pragma unroll
                for (int grp = 0; grp < NG; grp++) {
                    int cn = (wn + grp * 16 + lsel * 8) >> 3;
                    uint32_t woff = (uint32_t)(kr * (NBLK * 2) + ((cn ^ kx) << 4));
                    ldmx4t(&wr[grp * 4], sbase + OFF_W + buf * wchunk + woff);
                }
#pragma unroll
                for (int mi = 0; mi < 4; mi++)
#pragma unroll
                    for (int nj = 0; nj < NT; nj++)
                        mma_f16(acc[mi][nj], a[mi], &wr[nj * 2]);
            }
        }

        int bcol = (blockIdx.x * NITER + nb) * NBLK;
#pragma unroll
        for (int mi = 0; mi < 4; mi++) {
            int row = mrow0 + wm + mi * 16 + g4;
#pragma unroll
            for (int nj = 0; nj < NT; nj++) {
                int col = bcol + wn + nj * 8 + tig * 2;
                if (OUTF16) {
                    __half* Ch = (__half*)Cv;
                    if (row < M)
                        *(__half2*)(Ch + (size_t)row * N + col) =
                            __floats2half2_rn(acc[mi][nj][0], acc[mi][nj][1]);
                    if (row + 8 < M)
                        *(__half2*)(Ch + (size_t)(row + 8) * N + col) =
                            __floats2half2_rn(acc[mi][nj][2], acc[mi][nj][3]);
                } else {
                    float* Cf = (float*)Cv;
                    if (row < M)
                        *(float2*)(Cf + (size_t)row * N + col) =
                            make_float2(acc[mi][nj][0], acc[mi][nj][1]);
                    if (row + 8 < M)
                        *(float2*)(Cf + (size_t)(row + 8) * N + col) =
                            make_float2(acc[mi][nj][2], acc[mi][nj][3]);
                }
            }
        }

        if (STATS) {
            __shared__ float sp_s[8][WN], sp_q[8][WN];
#pragma unroll
            for (int nj = 0; nj < NT; nj++) {
                float c0 = 0.f, c1 = 0.f, q0 = 0.f, q1 = 0.f;
#pragma unroll
                for (int mi = 0; mi < 4; mi++) {
                    c0 += acc[mi][nj][0] + acc[mi][nj][2];
                    c1 += acc[mi][nj][1] + acc[mi][nj][3];
                    q0 += acc[mi][nj][0] * acc[mi][nj][0] +
                          acc[mi][nj][2] * acc[mi][nj][2];
                    q1 += acc[mi][nj][1] * acc[mi][nj][1] +
                          acc[mi][nj][3] * acc[mi][nj][3];
                }
#pragma unroll
                for (int o = 4; o < 32; o <<= 1) {
                    c0 += __shfl_xor_sync(0xffffffffu, c0, o);
                    c1 += __shfl_xor_sync(0xffffffffu, c1, o);
                    q0 += __shfl_xor_sync(0xffffffffu, q0, o);
                    q1 += __shfl_xor_sync(0xffffffffu, q1, o);
                }
                if (lane < 4) {
                    sp_s[wid][nj * 8 + lane * 2 + 0] = c0;
                    sp_s[wid][nj * 8 + lane * 2 + 1] = c1;
                    sp_q[wid][nj * 8 + lane * 2 + 0] = q0;
                    sp_q[wid][nj * 8 + lane * 2 + 1] = q1;
                }
            }
            __syncthreads();
            if (tid < NBLK) {
                int p = tid / WN, lc = tid % WN;
                float s = sp_s[p][lc] + sp_s[p + 4][lc];
                float q = sp_q[p][lc] + sp_q[p + 4][lc];
                atomicAdd(&psum_out[bcol + tid], s);
                atomicAdd(&psumsq_out[bcol + tid], q);
            }
            __syncthreads();
        }
    }
}

__global__ void decode_kernel(const float* __restrict__ z,
                              const int* __restrict__ pe,
                              const int* __restrict__ ne,
                              const float* __restrict__ gamma,
                              const float* __restrict__ beta,
                              const float* __restrict__ psum,
                              const float* __restrict__ psumsq,
                              float* __restrict__ out, int P, int Q, int n) {
    __shared__ float s_sc[64], s_sh[64];
    int tid = threadIdx.x;
    if (tid < 64) {
        float invn = 1.f / (float)n;
        float m = psum[tid] * invn;
        float var = psumsq[tid] * invn - m * m;
        float sc = gamma[tid] * rsqrtf(var + EPS);
        s_sc[tid] = sc;
        s_sh[tid] = beta[tid] - m * sc;
    }
    __syncthreads();
    int idx = blockIdx.x * blockDim.x + tid;
    int eg = idx >> 4;
    int l = idx & 15;
    if (eg >= P + Q) return;
    int a, b;
    if (eg < P) { a = pe[eg];     b = pe[P + eg]; }
    else        { int e = eg - P; a = ne[e]; b = ne[Q + e]; }
    float4 sc = ((const float4*)s_sc)[l];
    float4 sh = ((const float4*)s_sh)[l];
    float4 xa = ((const float4*)(z + (size_t)a * 64))[l];
    float4 xb = ((const float4*)(z + (size_t)b * 64))[l];
    xa.x = xa.x * sc.x + sh.x; xa.y = xa.y * sc.y + sh.y;
    xa.z = xa.z * sc.z + sh.z; xa.w = xa.w * sc.w + sh.w;
    xb.x = xb.x * sc.x + sh.x; xb.y = xb.y * sc.y + sh.y;
    xb.z = xb.z * sc.z + sh.z; xb.w = xb.w * sc.w + sh.w;
    float s = xa.x * xb.x + xa.y * xb.y + xa.z * xb.z + xa.w * xb.w;
    s += __shfl_xor_sync(0xffffffffu, s, 8);
    s += __shfl_xor_sync(0xffffffffu, s, 4);
    s += __shfl_xor_sync(0xffffffffu, s, 2);
    s += __shfl_xor_sync(0xffffffffu, s, 1);
    if (l == 0) out[eg] = s;
}

extern "C" void kernel_launch(void* const* d_in, const int* in_sizes, int n_in,
                              void* d_out, int out_size) {
    const float* x  = (const float*)d_in[0];
    const int*   ei = (const int*)d_in[1];
    const int*   pe = (const int*)d_in[2];
    const int*   ne = (const int*)d_in[3];
    const float* W1 = (const float*)d_in[4];
    const float* g1 = (const float*)d_in[6];
    const float* be1= (const float*)d_in[7];
    const float* W2 = (const float*)d_in[8];
    const float* g2 = (const float*)d_in[10];
    const float* be2= (const float*)d_in[11];
    const float* W3 = (const float*)d_in[12];
    const float* g3 = (const float*)d_in[14];
    const float* be3= (const float*)d_in[15];

    int N = in_sizes[0] / 128;
    int E = in_sizes[1] / 2;
    int P = in_sizes[2] / 2;
    int Q = in_sizes[3] / 2;

    float* bufA; float* bufB; uint8_t* wimg; float* sum; float* sumsq;
    cudaGetSymbolAddress((void**)&bufA, g_bufA);
    cudaGetSymbolAddress((void**)&bufB, g_bufB);
    cudaGetSymbolAddress((void**)&wimg, g_wimg);
    cudaGetSymbolAddress((void**)&sum, g_sum);
    cudaGetSymbolAddress((void**)&sumsq, g_sumsq);

    __half* x16 = (__half*)bufA;                       // N x 128 fp16
    __half* a1  = (__half*)(bufA + 6400000);           // N x 128 fp16 (agg1 out)
    __half* h1  = (__half*)bufB;                       // N x 256 fp16 (gemm1 out)
    __half* h2  = (__half*)(bufB + 12800000);          // N x 128 fp16 (gemm2 out)
    __half* b2h = (__half*)bufA;                       // N x 128 fp16 (agg2 out; x16 dead)
    __half* h3  = (__half*)(bufB + 19200000);          // N x 64 fp16 (gemm3 out)
    float*  z   = bufB;                                // N x 64 fp32 (agg3 out)

    float* out = (float*)d_out;

    int nb = (N + 255) / 256;
    int eb4 = (E / 4 + 255) / 256;
    int xb = (N * 16 + 255) / 256;
    int aggB256 = (N * 32 + 255) / 256;
    int aggB1024 = (N + 31) / 32;
    int mtiles = (N + 127) / 128;

    const int SMEM_L1 = 1024 + 32768 + 2 * 32768;
    const int SMEM_L2 = 1024 + 32768 + 2 * 32768;
    const int SMEM_L3 = 1024 + 32768 + 16384;
    cudaFuncSetAttribute((const void*)mma_gemm_kernel<128, 2, 1, 1, 0, 1, 1>,
                         cudaFuncAttributeMaxDynamicSharedMemorySize, SMEM_L1);
    cudaFuncSetAttribute((const void*)mma_gemm_kernel<128, 1, 2, 1, 1, 0, 1>,
                         cudaFuncAttributeMaxDynamicSharedMemorySize, SMEM_L2);
    cudaFuncSetAttribute((const void*)mma_gemm_kernel<64, 1, 1, 1, 1, 0, 1>,
                         cudaFuncAttributeMaxDynamicSharedMemorySize, SMEM_L3);

    // ---- prep (zero + W images) / combo (scatter || x->fp16) / agg1 ----
    prep_kernel<<<nb + 288, 256>>>(W1, W2, W3, wimg, N, nb);               // 0
    combo_kernel<<<eb4 + xb, 256>>>(ei, ei + E, E, eb4, x, x16, N * 16);   // 1
    agg128_f16_kernel<<<aggB256, 256>>>(x16, a1, N);                       // 2

    // ---- Layer 1: GEMM fp16 (stats -> sum[0:256]) ----
    mma_gemm_kernel<128, 2, 1, 1, 0, 1, 1><<<dim3(1, mtiles), 256, SMEM_L1>>>(
        a1, wimg + 0, h1, nullptr, nullptr, nullptr, nullptr,
        sum, sumsq, N);                                                    // 3 <- profiled

    // ---- Layer 2: GEMM (BN1+sigmoid inline) -> agg (fp16 out, stats) ----
    mma_gemm_kernel<128, 1, 2, 1, 1, 0, 1><<<dim3(1, mtiles), 256, SMEM_L2>>>(
        h1, wimg + 65536, h2, g1, be1, sum, sumsq,
        nullptr, nullptr, N);                                              // 4
    agg128_stats_f16_kernel<<<aggB1024, 1024>>>(h2, b2h, sum + 256, sumsq + 256, N);  // 5

    // ---- Layer 3: GEMM (BN2+sigmoid inline, fp16 A) -> agg64 (stats) ----
    mma_gemm_kernel<64, 1, 1, 1, 1, 0, 1><<<dim3(1, mtiles), 256, SMEM_L3>>>(
        b2h, wimg + 131072, h3, g2, be2, sum + 256, sumsq + 256,
        nullptr, nullptr, N);                                              // 6
    agg64_stats_f16_kernel<<<aggB1024, 1024>>>(h3, z, sum + 384, sumsq + 384, N);     // 7

    // ---- Decode (BN3 finalize + affine inlined, fp32 z) ----
    {
        int tot = (P + Q) * 16;
        decode_kernel<<<(tot + 255) / 256, 256>>>(
            z, pe, ne, g3, be3, sum + 384, sumsq + 384, out, P, Q, N);     // 8
    }
}